// round 3
// baseline (speedup 1.0000x reference)
#include <cuda_runtime.h>
#include <cstdint>

#define D_IN      128
#define E_DIM     64
#define TOTAL     320      // 2*D_IN + E_DIM
#define HEADS     8
#define MAX_NODES 100000

// ---- scratch (__device__ globals — no allocations allowed) ----
__device__ float g_weff_node[256 * HEADS];   // Weff rows 0..255, layout [d][h]
__device__ float g_weffE[E_DIM * HEADS];     // Weff rows 256..319, layout [k][h]
__device__ float g_beff[HEADS];              // b1 @ W2 + b2
__device__ float g_proj[MAX_NODES * 16];     // per-node: 8 origin-proj + 8 dest-proj

// ============================================================================
// Kernel 1: Weff = W1 @ W2  (320x8), beff = b1 @ W2 + b2.   One warp per output.
// ============================================================================
__global__ void prep_kernel(const float* __restrict__ W1, const float* __restrict__ b1,
                            const float* __restrict__ W2, const float* __restrict__ b2) {
    int w    = (blockIdx.x * blockDim.x + threadIdx.x) >> 5;
    int lane = threadIdx.x & 31;
    if (w >= TOTAL * HEADS + HEADS) return;

    float s = 0.0f;
    if (w < TOTAL * HEADS) {
        int i = w >> 3;      // Weff row (0..319)
        int h = w & 7;       // head
        #pragma unroll
        for (int t = 0; t < 10; t++) {
            int j = lane + 32 * t;
            s += W1[i * TOTAL + j] * W2[j * HEADS + h];
        }
        #pragma unroll
        for (int o = 16; o > 0; o >>= 1) s += __shfl_down_sync(0xffffffffu, s, o);
        if (lane == 0) {
            if (i < 256) g_weff_node[i * HEADS + h] = s;
            else         g_weffE[(i - 256) * HEADS + h] = s;   // [k][h] layout
        }
    } else {
        int h = w - TOTAL * HEADS;
        #pragma unroll
        for (int t = 0; t < 10; t++) {
            int j = lane + 32 * t;
            s += b1[j] * W2[j * HEADS + h];
        }
        #pragma unroll
        for (int o = 16; o > 0; o >>= 1) s += __shfl_down_sync(0xffffffffu, s, o);
        if (lane == 0) g_beff[h] = s + b2[h];
    }
}

// ============================================================================
// Kernel 2: per-node projections.  One thread per node.
//   proj[n][0:8]  = x[n] @ Weff[0:128]     (origin part)
//   proj[n][8:16] = x[n] @ Weff[128:256]   (dest part)
// ============================================================================
__global__ __launch_bounds__(256) void node_proj_kernel(const float* __restrict__ x,
                                                        int n_nodes) {
    __shared__ float sw[256 * HEADS];   // 8 KB
    for (int i = threadIdx.x; i < 256 * HEADS; i += blockDim.x) sw[i] = g_weff_node[i];
    __syncthreads();

    int n = blockIdx.x * blockDim.x + threadIdx.x;
    if (n >= n_nodes) return;

    float acc_o[8], acc_d[8];
    #pragma unroll
    for (int h = 0; h < 8; h++) { acc_o[h] = 0.0f; acc_d[h] = 0.0f; }

    const float4* xr = reinterpret_cast<const float4*>(x + (size_t)n * D_IN);

    #pragma unroll 8
    for (int c = 0; c < D_IN / 4; c++) {       // 32 float4 loads
        float4 xv = __ldg(xr + c);
        float xs[4] = {xv.x, xv.y, xv.z, xv.w};
        #pragma unroll
        for (int j = 0; j < 4; j++) {
            int d = 4 * c + j;
            const float4* wo = reinterpret_cast<const float4*>(sw + d * HEADS);
            float4 w0 = wo[0], w1 = wo[1];
            acc_o[0] += xs[j] * w0.x;  acc_o[1] += xs[j] * w0.y;
            acc_o[2] += xs[j] * w0.z;  acc_o[3] += xs[j] * w0.w;
            acc_o[4] += xs[j] * w1.x;  acc_o[5] += xs[j] * w1.y;
            acc_o[6] += xs[j] * w1.z;  acc_o[7] += xs[j] * w1.w;
            const float4* wd = reinterpret_cast<const float4*>(sw + (128 + d) * HEADS);
            float4 v0 = wd[0], v1 = wd[1];
            acc_d[0] += xs[j] * v0.x;  acc_d[1] += xs[j] * v0.y;
            acc_d[2] += xs[j] * v0.z;  acc_d[3] += xs[j] * v0.w;
            acc_d[4] += xs[j] * v1.x;  acc_d[5] += xs[j] * v1.y;
            acc_d[6] += xs[j] * v1.z;  acc_d[7] += xs[j] * v1.w;
        }
    }

    float4* pr = reinterpret_cast<float4*>(g_proj + (size_t)n * 16);
    pr[0] = make_float4(acc_o[0], acc_o[1], acc_o[2], acc_o[3]);
    pr[1] = make_float4(acc_o[4], acc_o[5], acc_o[6], acc_o[7]);
    pr[2] = make_float4(acc_d[0], acc_d[1], acc_d[2], acc_d[3]);
    pr[3] = make_float4(acc_d[4], acc_d[5], acc_d[6], acc_d[7]);
}

// ============================================================================
// Kernel 3: edge pass, SPLIT-K.  8 lanes per edge; lane j owns k-chunk
// [8j, 8j+8) of the ee row (2 float4 loads — row read exactly once,
// 1024B contiguous per warp) and accumulates partials for ALL 8 heads
// against a register-resident [k][h] weight slice.  A 3-stage butterfly
// (xor 4/2/1) transposes+reduces so lane j finishes holding head j.
// ============================================================================
__global__ __launch_bounds__(256) void edge_kernel(const int* __restrict__ ei,
                                                   const float* __restrict__ ee,
                                                   float* __restrict__ out,
                                                   int n_edges, int n_groups) {
    int tid = blockIdx.x * blockDim.x + threadIdx.x;
    int j   = tid & 7;

    // Weight slice: rows k = 8j .. 8j+7 of g_weffE[64][8]  -> 64 floats
    float wr[64];
    const float4* wp = reinterpret_cast<const float4*>(g_weffE + j * 64);
    #pragma unroll
    for (int i = 0; i < 16; i++) {
        float4 v = wp[i];
        wr[4 * i + 0] = v.x; wr[4 * i + 1] = v.y;
        wr[4 * i + 2] = v.z; wr[4 * i + 3] = v.w;
    }
    float bh = g_beff[j];

    for (int e = tid >> 3; e < n_edges; e += n_groups) {
        const float4* er = reinterpret_cast<const float4*>(ee + (size_t)e * E_DIM + j * 8);
        float4 e0 = __ldg(er);
        float4 e1 = __ldg(er + 1);
        float ev[8] = {e0.x, e0.y, e0.z, e0.w, e1.x, e1.y, e1.z, e1.w};

        float acc[8];
        #pragma unroll
        for (int h = 0; h < 8; h++) acc[h] = ev[0] * wr[h];
        #pragma unroll
        for (int k = 1; k < 8; k++) {
            #pragma unroll
            for (int h = 0; h < 8; h++) acc[h] += ev[k] * wr[k * 8 + h];
        }

        // Butterfly transpose+reduce over the 8-lane group.
        int off = (j & 4) ? 4 : 0;
        float r4[4];
        #pragma unroll
        for (int m = 0; m < 4; m++) {
            float v = __shfl_xor_sync(0xffffffffu, acc[m + (off ^ 4)], 4);
            r4[m] = acc[m + off] + v;
        }
        int off2 = (j & 2) ? 2 : 0;
        float r2[2];
        #pragma unroll
        for (int m = 0; m < 2; m++) {
            float v = __shfl_xor_sync(0xffffffffu, r4[m + (off2 ^ 2)], 2);
            r2[m] = r4[m + off2] + v;
        }
        int   off3 = j & 1;
        float v    = __shfl_xor_sync(0xffffffffu, r2[off3 ^ 1], 1);
        float res  = r2[off3] + v;   // = sum over all k of ee.w[:, j]

        int o = __ldg(ei + e);
        int d = __ldg(ei + n_edges + e);
        res += g_proj[(size_t)o * 16 + j] + g_proj[(size_t)d * 16 + 8 + j] + bh;
        out[(size_t)e * HEADS + j] = res;
    }
}

// ============================================================================
// launcher
// ============================================================================
extern "C" void kernel_launch(void* const* d_in, const int* in_sizes, int n_in,
                              void* d_out, int out_size) {
    const float* x   = (const float*)d_in[0];
    const int*   ei  = (const int*)d_in[1];
    const float* ee  = (const float*)d_in[2];
    const float* W1  = (const float*)d_in[3];
    const float* b1  = (const float*)d_in[4];
    const float* W2  = (const float*)d_in[5];
    const float* b2  = (const float*)d_in[6];
    float*       out = (float*)d_out;

    int n_nodes = in_sizes[0] / D_IN;
    int n_edges = in_sizes[1] / 2;

    // K1: Weff/beff prep
    {
        int warps   = TOTAL * HEADS + HEADS;
        int threads = warps * 32;
        int blocks  = (threads + 255) / 256;
        prep_kernel<<<blocks, 256>>>(W1, b1, W2, b2);
    }

    // K2: node projections — one thread per node
    {
        int blocks = (n_nodes + 255) / 256;
        node_proj_kernel<<<blocks, 256>>>(x, n_nodes);
    }

    // K3: edge pass — persistent, split-K, 8 lanes per edge
    {
        int blocks   = 1184;              // ~8 blocks/SM
        int threads  = 256;
        int n_groups = blocks * threads / 8;
        edge_kernel<<<blocks, threads>>>(ei, ee, out, n_edges, n_groups);
    }
}

// round 5
// speedup vs baseline: 1.4086x; 1.4086x over previous
#include <cuda_runtime.h>
#include <cstdint>

#define D_IN      128
#define E_DIM     64
#define TOTAL     320      // 2*D_IN + E_DIM
#define HEADS     8
#define MAX_NODES 100000
#define TILE_E    128      // edges staged per block iteration
#define ROW_PAD   68       // floats per padded smem row (breaks 256B-stride conflicts)

// ---- scratch (__device__ globals — no allocations allowed) ----
__device__ float g_weff_node[256 * HEADS];   // Weff rows 0..255, layout [d][h]
__device__ float g_weffE[E_DIM * HEADS];     // Weff rows 256..319, layout [k][h]
__device__ float g_beff[HEADS];              // b1 @ W2 + b2
__device__ float g_proj[MAX_NODES * 16];     // per-node: 8 origin-proj + 8 dest-proj

// ============================================================================
// Kernel 1: Weff = W1 @ W2  (320x8), beff = b1 @ W2 + b2.   One warp per output.
// ============================================================================
__global__ void prep_kernel(const float* __restrict__ W1, const float* __restrict__ b1,
                            const float* __restrict__ W2, const float* __restrict__ b2) {
    int w    = (blockIdx.x * blockDim.x + threadIdx.x) >> 5;
    int lane = threadIdx.x & 31;
    if (w >= TOTAL * HEADS + HEADS) return;

    float s = 0.0f;
    if (w < TOTAL * HEADS) {
        int i = w >> 3;      // Weff row (0..319)
        int h = w & 7;       // head
        #pragma unroll
        for (int t = 0; t < 10; t++) {
            int j = lane + 32 * t;
            s += W1[i * TOTAL + j] * W2[j * HEADS + h];
        }
        #pragma unroll
        for (int o = 16; o > 0; o >>= 1) s += __shfl_down_sync(0xffffffffu, s, o);
        if (lane == 0) {
            if (i < 256) g_weff_node[i * HEADS + h] = s;
            else         g_weffE[(i - 256) * HEADS + h] = s;   // [k][h] layout
        }
    } else {
        int h = w - TOTAL * HEADS;
        #pragma unroll
        for (int t = 0; t < 10; t++) {
            int j = lane + 32 * t;
            s += b1[j] * W2[j * HEADS + h];
        }
        #pragma unroll
        for (int o = 16; o > 0; o >>= 1) s += __shfl_down_sync(0xffffffffu, s, o);
        if (lane == 0) g_beff[h] = s + b2[h];
    }
}

// ============================================================================
// Kernel 2: per-node projections.  One thread per node.  (known-good version)
// ============================================================================
__global__ __launch_bounds__(256) void node_proj_kernel(const float* __restrict__ x,
                                                        int n_nodes) {
    __shared__ float sw[256 * HEADS];   // 8 KB
    for (int i = threadIdx.x; i < 256 * HEADS; i += blockDim.x) sw[i] = g_weff_node[i];
    __syncthreads();

    int n = blockIdx.x * blockDim.x + threadIdx.x;
    if (n >= n_nodes) return;

    float acc_o[8], acc_d[8];
    #pragma unroll
    for (int h = 0; h < 8; h++) { acc_o[h] = 0.0f; acc_d[h] = 0.0f; }

    const float4* xr = reinterpret_cast<const float4*>(x + (size_t)n * D_IN);

    for (int c = 0; c < D_IN / 4; c++) {       // 32 float4 loads
        float4 xv = __ldg(xr + c);
        float xs[4] = {xv.x, xv.y, xv.z, xv.w};
        #pragma unroll
        for (int j = 0; j < 4; j++) {
            int d = 4 * c + j;
            const float4* wo = reinterpret_cast<const float4*>(sw + d * HEADS);
            float4 w0 = wo[0], w1 = wo[1];
            acc_o[0] += xs[j] * w0.x;  acc_o[1] += xs[j] * w0.y;
            acc_o[2] += xs[j] * w0.z;  acc_o[3] += xs[j] * w0.w;
            acc_o[4] += xs[j] * w1.x;  acc_o[5] += xs[j] * w1.y;
            acc_o[6] += xs[j] * w1.z;  acc_o[7] += xs[j] * w1.w;
            const float4* wd = reinterpret_cast<const float4*>(sw + (128 + d) * HEADS);
            float4 v0 = wd[0], v1 = wd[1];
            acc_d[0] += xs[j] * v0.x;  acc_d[1] += xs[j] * v0.y;
            acc_d[2] += xs[j] * v0.z;  acc_d[3] += xs[j] * v0.w;
            acc_d[4] += xs[j] * v1.x;  acc_d[5] += xs[j] * v1.y;
            acc_d[6] += xs[j] * v1.z;  acc_d[7] += xs[j] * v1.w;
        }
    }

    float4* pr = reinterpret_cast<float4*>(g_proj + (size_t)n * 16);
    pr[0] = make_float4(acc_o[0], acc_o[1], acc_o[2], acc_o[3]);
    pr[1] = make_float4(acc_o[4], acc_o[5], acc_o[6], acc_o[7]);
    pr[2] = make_float4(acc_d[0], acc_d[1], acc_d[2], acc_d[3]);
    pr[3] = make_float4(acc_d[4], acc_d[5], acc_d[6], acc_d[7]);
}

// ============================================================================
// Kernel 3: edge pass, smem-staged.
//   - Tile of 128 edge rows staged into smem with fully coalesced float4 loads
//     (2 L1 wavefronts/edge — the floor), rows padded to 68 floats.
//   - One thread per edge: 8 independent accumulator chains, weights broadcast
//     from smem [k][h].  No register weight arrays, no shuffles.
//   - proj gathers issued before the dot product to overlap L2 latency.
// ============================================================================
__global__ __launch_bounds__(TILE_E) void edge_kernel(const int* __restrict__ ei,
                                                      const float* __restrict__ ee,
                                                      float* __restrict__ out,
                                                      int n_edges, int n_tiles) {
    __shared__ float swE[E_DIM * HEADS];        // 2 KB, [k][h]
    __shared__ float stile[TILE_E * ROW_PAD];   // 34.8 KB

    int t = threadIdx.x;

    // weights + bias (512 floats = 128 float4; one per thread)
    reinterpret_cast<float4*>(swE)[t] = reinterpret_cast<const float4*>(g_weffE)[t];
    float bh[8];
    #pragma unroll
    for (int h = 0; h < 8; h++) bh[h] = g_beff[h];
    __syncthreads();

    const float4* ee4 = reinterpret_cast<const float4*>(ee);
    long total_f4 = (long)n_edges * 16;

    for (int tile = blockIdx.x; tile < n_tiles; tile += gridDim.x) {
        long base_f4 = (long)tile * TILE_E * 16;

        // ---- stage: 2048 float4, coalesced; thread t takes f = i*128 + t ----
        #pragma unroll
        for (int i = 0; i < 16; i++) {
            int f = i * TILE_E + t;
            float4 v = (base_f4 + f < total_f4) ? __ldg(ee4 + base_f4 + f)
                                                : make_float4(0.f, 0.f, 0.f, 0.f);
            int row = f >> 4;            // 16 float4 per row
            int col = f & 15;
            *reinterpret_cast<float4*>(stile + row * ROW_PAD + col * 4) = v;
        }
        __syncthreads();

        // ---- compute: one thread per edge ----
        int e = tile * TILE_E + t;
        if (e < n_edges) {
            int o = __ldg(ei + e);
            int d = __ldg(ei + n_edges + e);
            const float4* po = reinterpret_cast<const float4*>(g_proj + (size_t)o * 16);
            const float4* pd = reinterpret_cast<const float4*>(g_proj + (size_t)d * 16 + 8);
            float4 a0 = __ldg(po), a1 = __ldg(po + 1);
            float4 b0 = __ldg(pd), b1 = __ldg(pd + 1);

            float acc[8];
            acc[0] = a0.x + b0.x + bh[0];  acc[1] = a0.y + b0.y + bh[1];
            acc[2] = a0.z + b0.z + bh[2];  acc[3] = a0.w + b0.w + bh[3];
            acc[4] = a1.x + b1.x + bh[4];  acc[5] = a1.y + b1.y + bh[5];
            acc[6] = a1.z + b1.z + bh[6];  acc[7] = a1.w + b1.w + bh[7];

            const float* rowp = stile + t * ROW_PAD;
            #pragma unroll
            for (int c = 0; c < 16; c++) {
                float4 v = *reinterpret_cast<const float4*>(rowp + c * 4);
                float vs[4] = {v.x, v.y, v.z, v.w};
                #pragma unroll
                for (int j = 0; j < 4; j++) {
                    int k = c * 4 + j;
                    const float4* w = reinterpret_cast<const float4*>(swE + k * 8);
                    float4 w0 = w[0], w1 = w[1];
                    acc[0] += vs[j] * w0.x;  acc[1] += vs[j] * w0.y;
                    acc[2] += vs[j] * w0.z;  acc[3] += vs[j] * w0.w;
                    acc[4] += vs[j] * w1.x;  acc[5] += vs[j] * w1.y;
                    acc[6] += vs[j] * w1.z;  acc[7] += vs[j] * w1.w;
                }
            }

            float4* op = reinterpret_cast<float4*>(out + (size_t)e * HEADS);
            op[0] = make_float4(acc[0], acc[1], acc[2], acc[3]);
            op[1] = make_float4(acc[4], acc[5], acc[6], acc[7]);
        }
        __syncthreads();
    }
}

// ============================================================================
// launcher
// ============================================================================
extern "C" void kernel_launch(void* const* d_in, const int* in_sizes, int n_in,
                              void* d_out, int out_size) {
    const float* x   = (const float*)d_in[0];
    const int*   ei  = (const int*)d_in[1];
    const float* ee  = (const float*)d_in[2];
    const float* W1  = (const float*)d_in[3];
    const float* b1  = (const float*)d_in[4];
    const float* W2  = (const float*)d_in[5];
    const float* b2  = (const float*)d_in[6];
    float*       out = (float*)d_out;

    int n_nodes = in_sizes[0] / D_IN;
    int n_edges = in_sizes[1] / 2;

    // K1: Weff/beff prep
    {
        int warps   = TOTAL * HEADS + HEADS;
        int threads = warps * 32;
        int blocks  = (threads + 255) / 256;
        prep_kernel<<<blocks, 256>>>(W1, b1, W2, b2);
    }

    // K2: node projections — one thread per node
    {
        int blocks = (n_nodes + 255) / 256;
        node_proj_kernel<<<blocks, 256>>>(x, n_nodes);
    }

    // K3: edge pass — smem-staged tiles, one thread per edge
    {
        int n_tiles = (n_edges + TILE_E - 1) / TILE_E;
        int blocks  = 888;                  // 148 SMs x 6 resident blocks
        if (blocks > n_tiles) blocks = n_tiles;
        edge_kernel<<<blocks, TILE_E>>>(ei, ee, out, n_edges, n_tiles);
    }
}

// round 6
// speedup vs baseline: 1.4762x; 1.0480x over previous
#include <cuda_runtime.h>
#include <cstdint>

#define D_IN      128
#define E_DIM     64
#define TOTAL     320      // 2*D_IN + E_DIM
#define HEADS     8
#define MAX_NODES 100000
#define TILE_E    128      // edges per tile buffer
#define ROW_PAD   68       // floats per padded smem row (272B = 17*16, cp.async-alignable)

// ---- scratch (__device__ globals — no allocations allowed) ----
__device__ float g_weff_node[256 * HEADS];   // Weff rows 0..255, layout [d][h]
__device__ float g_weffE[E_DIM * HEADS];     // Weff rows 256..319, layout [k][h]
__device__ float g_beff[HEADS];              // b1 @ W2 + b2
__device__ float g_proj[MAX_NODES * 16];     // per-node: 8 origin-proj + 8 dest-proj

static __device__ __forceinline__ uint32_t smem_u32(const void* p) {
    return (uint32_t)__cvta_generic_to_shared(p);
}

// ============================================================================
// Kernel 1: Weff = W1 @ W2  (320x8), beff = b1 @ W2 + b2.   One warp per output.
// ============================================================================
__global__ void prep_kernel(const float* __restrict__ W1, const float* __restrict__ b1,
                            const float* __restrict__ W2, const float* __restrict__ b2) {
    int w    = (blockIdx.x * blockDim.x + threadIdx.x) >> 5;
    int lane = threadIdx.x & 31;
    if (w >= TOTAL * HEADS + HEADS) return;

    float s = 0.0f;
    if (w < TOTAL * HEADS) {
        int i = w >> 3;      // Weff row (0..319)
        int h = w & 7;       // head
        #pragma unroll
        for (int t = 0; t < 10; t++) {
            int j = lane + 32 * t;
            s += W1[i * TOTAL + j] * W2[j * HEADS + h];
        }
        #pragma unroll
        for (int o = 16; o > 0; o >>= 1) s += __shfl_down_sync(0xffffffffu, s, o);
        if (lane == 0) {
            if (i < 256) g_weff_node[i * HEADS + h] = s;
            else         g_weffE[(i - 256) * HEADS + h] = s;   // [k][h] layout
        }
    } else {
        int h = w - TOTAL * HEADS;
        #pragma unroll
        for (int t = 0; t < 10; t++) {
            int j = lane + 32 * t;
            s += b1[j] * W2[j * HEADS + h];
        }
        #pragma unroll
        for (int o = 16; o > 0; o >>= 1) s += __shfl_down_sync(0xffffffffu, s, o);
        if (lane == 0) g_beff[h] = s + b2[h];
    }
}

// ============================================================================
// Kernel 2: per-node projections.  One thread per node.  (known-good version)
// ============================================================================
__global__ __launch_bounds__(256) void node_proj_kernel(const float* __restrict__ x,
                                                        int n_nodes) {
    __shared__ float sw[256 * HEADS];   // 8 KB
    for (int i = threadIdx.x; i < 256 * HEADS; i += blockDim.x) sw[i] = g_weff_node[i];
    __syncthreads();

    int n = blockIdx.x * blockDim.x + threadIdx.x;
    if (n >= n_nodes) return;

    float acc_o[8], acc_d[8];
    #pragma unroll
    for (int h = 0; h < 8; h++) { acc_o[h] = 0.0f; acc_d[h] = 0.0f; }

    const float4* xr = reinterpret_cast<const float4*>(x + (size_t)n * D_IN);

    for (int c = 0; c < D_IN / 4; c++) {       // 32 float4 loads
        float4 xv = __ldg(xr + c);
        float xs[4] = {xv.x, xv.y, xv.z, xv.w};
        #pragma unroll
        for (int j = 0; j < 4; j++) {
            int d = 4 * c + j;
            const float4* wo = reinterpret_cast<const float4*>(sw + d * HEADS);
            float4 w0 = wo[0], w1 = wo[1];
            acc_o[0] += xs[j] * w0.x;  acc_o[1] += xs[j] * w0.y;
            acc_o[2] += xs[j] * w0.z;  acc_o[3] += xs[j] * w0.w;
            acc_o[4] += xs[j] * w1.x;  acc_o[5] += xs[j] * w1.y;
            acc_o[6] += xs[j] * w1.z;  acc_o[7] += xs[j] * w1.w;
            const float4* wd = reinterpret_cast<const float4*>(sw + (128 + d) * HEADS);
            float4 v0 = wd[0], v1 = wd[1];
            acc_d[0] += xs[j] * v0.x;  acc_d[1] += xs[j] * v0.y;
            acc_d[2] += xs[j] * v0.z;  acc_d[3] += xs[j] * v0.w;
            acc_d[4] += xs[j] * v1.x;  acc_d[5] += xs[j] * v1.y;
            acc_d[6] += xs[j] * v1.z;  acc_d[7] += xs[j] * v1.w;
        }
    }

    float4* pr = reinterpret_cast<float4*>(g_proj + (size_t)n * 16);
    pr[0] = make_float4(acc_o[0], acc_o[1], acc_o[2], acc_o[3]);
    pr[1] = make_float4(acc_o[4], acc_o[5], acc_o[6], acc_o[7]);
    pr[2] = make_float4(acc_d[0], acc_d[1], acc_d[2], acc_d[3]);
    pr[3] = make_float4(acc_d[4], acc_d[5], acc_d[6], acc_d[7]);
}

// ============================================================================
// Kernel 3: edge pass, cp.async DOUBLE-BUFFERED.
//   Tile i+1 (ee rows + edge indices) streams from DRAM via cp.async while
//   tile i computes.  One thread per edge; weights broadcast from smem [k][h];
//   8 independent FMA chains; no shuffles.
// Dynamic smem layout (floats):
//   [0,512)         swE  (2 KB)
//   [512,1024)      sei  (2 bufs x 256 ints: 128 origin + 128 dest)
//   [1024, +2*8704) stile (2 bufs x 128 rows x 68 floats)
// ============================================================================
#define STILE_BUF (TILE_E * ROW_PAD)          // 8704 floats
#define SMEM_FLOATS (1024 + 2 * STILE_BUF)    // 18432 floats = 73728 B

__global__ __launch_bounds__(TILE_E) void edge_kernel(const int* __restrict__ ei,
                                                      const float* __restrict__ ee,
                                                      float* __restrict__ out,
                                                      int n_edges, int n_tiles) {
    extern __shared__ float smem[];
    float* swE   = smem;                       // 512 floats
    int*   sei   = (int*)(smem + 512);         // 512 ints
    float* stile = smem + 1024;

    int t = threadIdx.x;

    // weights (512 floats = 128 float4, one per thread) + bias
    reinterpret_cast<float4*>(swE)[t] = reinterpret_cast<const float4*>(g_weffE)[t];
    float bh[8];
    #pragma unroll
    for (int h = 0; h < 8; h++) bh[h] = g_beff[h];

    const float4* ee4 = reinterpret_cast<const float4*>(ee);
    long total_f4 = (long)n_edges * 16;

    auto stage = [&](int buf, int tile) {
        if (tile < n_tiles) {
            long base = (long)tile * TILE_E * 16;
            float* dstb = stile + buf * STILE_BUF;
            #pragma unroll
            for (int i = 0; i < 16; i++) {
                int f   = i * TILE_E + t;
                int row = f >> 4;
                int col = f & 15;
                uint32_t d = smem_u32(dstb + row * ROW_PAD + col * 4);
                const float4* s = ee4 + base + f;
                int sz = (base + f < total_f4) ? 16 : 0;
                asm volatile("cp.async.cg.shared.global [%0], [%1], 16, %2;\n"
                             :: "r"(d), "l"(s), "r"(sz));
            }
            // indices: 256 ints (128 origin, 128 dest), 16B chunks by threads 0..63
            if (t < 64) {
                int half = t >> 5;           // 0 = origin, 1 = dest
                int q    = t & 31;
                int e0   = tile * TILE_E;
                const int* s = ei + (size_t)half * n_edges + e0 + q * 4;
                uint32_t d = smem_u32(sei + buf * 256 + half * 128 + q * 4);
                int rem = n_edges - (e0 + q * 4);
                int sz  = rem >= 4 ? 16 : (rem > 0 ? rem * 4 : 0);
                asm volatile("cp.async.cg.shared.global [%0], [%1], 16, %2;\n"
                             :: "r"(d), "l"(s), "r"(sz));
            }
        }
        asm volatile("cp.async.commit_group;\n");
    };

    int stride = gridDim.x;
    int tile   = blockIdx.x;
    stage(0, tile);
    stage(1, tile + stride);

    int buf = 0;
    for (; tile < n_tiles; tile += stride) {
        asm volatile("cp.async.wait_group 1;\n");
        __syncthreads();

        int e = tile * TILE_E + t;
        if (e < n_edges) {
            int o = sei[buf * 256 + t];
            int d = sei[buf * 256 + 128 + t];
            const float4* po = reinterpret_cast<const float4*>(g_proj + (size_t)o * 16);
            const float4* pd = reinterpret_cast<const float4*>(g_proj + (size_t)d * 16 + 8);
            float4 a0 = __ldg(po), a1 = __ldg(po + 1);
            float4 b0 = __ldg(pd), b1 = __ldg(pd + 1);

            float acc[8];
            acc[0] = a0.x + b0.x + bh[0];  acc[1] = a0.y + b0.y + bh[1];
            acc[2] = a0.z + b0.z + bh[2];  acc[3] = a0.w + b0.w + bh[3];
            acc[4] = a1.x + b1.x + bh[4];  acc[5] = a1.y + b1.y + bh[5];
            acc[6] = a1.z + b1.z + bh[6];  acc[7] = a1.w + b1.w + bh[7];

            const float* rowp = stile + buf * STILE_BUF + t * ROW_PAD;
            #pragma unroll
            for (int c = 0; c < 16; c++) {
                float4 v = *reinterpret_cast<const float4*>(rowp + c * 4);
                float vs[4] = {v.x, v.y, v.z, v.w};
                #pragma unroll
                for (int j = 0; j < 4; j++) {
                    int k = c * 4 + j;
                    const float4* w = reinterpret_cast<const float4*>(swE + k * 8);
                    float4 w0 = w[0], w1 = w[1];
                    acc[0] += vs[j] * w0.x;  acc[1] += vs[j] * w0.y;
                    acc[2] += vs[j] * w0.z;  acc[3] += vs[j] * w0.w;
                    acc[4] += vs[j] * w1.x;  acc[5] += vs[j] * w1.y;
                    acc[6] += vs[j] * w1.z;  acc[7] += vs[j] * w1.w;
                }
            }

            float4* op = reinterpret_cast<float4*>(out + (size_t)e * HEADS);
            op[0] = make_float4(acc[0], acc[1], acc[2], acc[3]);
            op[1] = make_float4(acc[4], acc[5], acc[6], acc[7]);
        }
        __syncthreads();                 // all reads of buf done before restaging

        stage(buf, tile + 2 * stride);   // prefetch two tiles ahead into freed buf
        buf ^= 1;
    }
}

// ============================================================================
// launcher
// ============================================================================
extern "C" void kernel_launch(void* const* d_in, const int* in_sizes, int n_in,
                              void* d_out, int out_size) {
    const float* x   = (const float*)d_in[0];
    const int*   ei  = (const int*)d_in[1];
    const float* ee  = (const float*)d_in[2];
    const float* W1  = (const float*)d_in[3];
    const float* b1  = (const float*)d_in[4];
    const float* W2  = (const float*)d_in[5];
    const float* b2  = (const float*)d_in[6];
    float*       out = (float*)d_out;

    int n_nodes = in_sizes[0] / D_IN;
    int n_edges = in_sizes[1] / 2;

    // Allow 72 KB dynamic smem for edge_kernel (idempotent; not a stream op).
    static bool attr_set = false;   // value identical every call -> deterministic
    if (!attr_set) {
        cudaFuncSetAttribute(edge_kernel, cudaFuncAttributeMaxDynamicSharedMemorySize,
                             SMEM_FLOATS * (int)sizeof(float));
        attr_set = true;
    }

    // K1: Weff/beff prep
    {
        int warps   = TOTAL * HEADS + HEADS;
        int threads = warps * 32;
        int blocks  = (threads + 255) / 256;
        prep_kernel<<<blocks, 256>>>(W1, b1, W2, b2);
    }

    // K2: node projections — one thread per node
    {
        int blocks = (n_nodes + 255) / 256;
        node_proj_kernel<<<blocks, 256>>>(x, n_nodes);
    }

    // K3: edge pass — cp.async double-buffered tiles
    {
        int n_tiles = (n_edges + TILE_E - 1) / TILE_E;
        int blocks  = 444;                  // 148 SMs x 3 resident (72KB smem each)
        if (blocks > n_tiles) blocks = n_tiles;
        edge_kernel<<<blocks, TILE_E, SMEM_FLOATS * (int)sizeof(float)>>>(
            ei, ee, out, n_edges, n_tiles);
    }
}

// round 11
// speedup vs baseline: 1.4800x; 1.0026x over previous
#include <cuda_runtime.h>
#include <cstdint>

#define D_IN      128
#define E_DIM     64
#define TOTAL     320      // 2*D_IN + E_DIM
#define HEADS     8
#define MAX_NODES 100000
#define TILE_E    128      // edges per tile buffer
#define ROW_PAD   68       // floats per padded smem row (272B)

// ---- scratch (__device__ globals — no allocations allowed) ----
__device__ float g_weff_node[256 * HEADS];   // Weff rows 0..255, layout [d][h]
__device__ float g_weffE[E_DIM * HEADS];     // Weff rows 256..319, layout [k][h]
__device__ float g_beff[HEADS];              // b1 @ W2 + b2
__device__ float g_proj[MAX_NODES * 16];     // per-node: 8 origin-proj + 8 dest-proj

static __device__ __forceinline__ uint32_t smem_u32(const void* p) {
    return (uint32_t)__cvta_generic_to_shared(p);
}

// ============================================================================
// Kernel 1: Weff = W1 @ W2  (320x8), beff = b1 @ W2 + b2.   One warp per output.
// ============================================================================
__global__ void prep_kernel(const float* __restrict__ W1, const float* __restrict__ b1,
                            const float* __restrict__ W2, const float* __restrict__ b2) {
    int w    = (blockIdx.x * blockDim.x + threadIdx.x) >> 5;
    int lane = threadIdx.x & 31;
    if (w >= TOTAL * HEADS + HEADS) return;

    float s = 0.0f;
    if (w < TOTAL * HEADS) {
        int i = w >> 3;      // Weff row (0..319)
        int h = w & 7;       // head
        #pragma unroll
        for (int t = 0; t < 10; t++) {
            int j = lane + 32 * t;
            s += W1[i * TOTAL + j] * W2[j * HEADS + h];
        }
        #pragma unroll
        for (int o = 16; o > 0; o >>= 1) s += __shfl_down_sync(0xffffffffu, s, o);
        if (lane == 0) {
            if (i < 256) g_weff_node[i * HEADS + h] = s;
            else         g_weffE[(i - 256) * HEADS + h] = s;   // [k][h] layout
        }
    } else {
        int h = w - TOTAL * HEADS;
        #pragma unroll
        for (int t = 0; t < 10; t++) {
            int j = lane + 32 * t;
            s += b1[j] * W2[j * HEADS + h];
        }
        #pragma unroll
        for (int o = 16; o > 0; o >>= 1) s += __shfl_down_sync(0xffffffffu, s, o);
        if (lane == 0) g_beff[h] = s + b2[h];
    }
}

// ============================================================================
// Kernel 2: per-node projections.  One thread per node.  (known-good version)
// ============================================================================
__global__ __launch_bounds__(256) void node_proj_kernel(const float* __restrict__ x,
                                                        int n_nodes) {
    __shared__ float sw[256 * HEADS];   // 8 KB
    for (int i = threadIdx.x; i < 256 * HEADS; i += blockDim.x) sw[i] = g_weff_node[i];
    __syncthreads();

    int n = blockIdx.x * blockDim.x + threadIdx.x;
    if (n >= n_nodes) return;

    float acc_o[8], acc_d[8];
    #pragma unroll
    for (int h = 0; h < 8; h++) { acc_o[h] = 0.0f; acc_d[h] = 0.0f; }

    const float4* xr = reinterpret_cast<const float4*>(x + (size_t)n * D_IN);

    for (int c = 0; c < D_IN / 4; c++) {       // 32 float4 loads
        float4 xv = __ldg(xr + c);
        float xs[4] = {xv.x, xv.y, xv.z, xv.w};
        #pragma unroll
        for (int j = 0; j < 4; j++) {
            int d = 4 * c + j;
            const float4* wo = reinterpret_cast<const float4*>(sw + d * HEADS);
            float4 w0 = wo[0], w1 = wo[1];
            acc_o[0] += xs[j] * w0.x;  acc_o[1] += xs[j] * w0.y;
            acc_o[2] += xs[j] * w0.z;  acc_o[3] += xs[j] * w0.w;
            acc_o[4] += xs[j] * w1.x;  acc_o[5] += xs[j] * w1.y;
            acc_o[6] += xs[j] * w1.z;  acc_o[7] += xs[j] * w1.w;
            const float4* wd = reinterpret_cast<const float4*>(sw + (128 + d) * HEADS);
            float4 v0 = wd[0], v1 = wd[1];
            acc_d[0] += xs[j] * v0.x;  acc_d[1] += xs[j] * v0.y;
            acc_d[2] += xs[j] * v0.z;  acc_d[3] += xs[j] * v0.w;
            acc_d[4] += xs[j] * v1.x;  acc_d[5] += xs[j] * v1.y;
            acc_d[6] += xs[j] * v1.z;  acc_d[7] += xs[j] * v1.w;
        }
    }

    float4* pr = reinterpret_cast<float4*>(g_proj + (size_t)n * 16);
    pr[0] = make_float4(acc_o[0], acc_o[1], acc_o[2], acc_o[3]);
    pr[1] = make_float4(acc_o[4], acc_o[5], acc_o[6], acc_o[7]);
    pr[2] = make_float4(acc_d[0], acc_d[1], acc_d[2], acc_d[3]);
    pr[3] = make_float4(acc_d[4], acc_d[5], acc_d[6], acc_d[7]);
}

// ============================================================================
// Kernel 3: edge pass, cp.async double-buffered (exact R6 staging + gathers);
// single delta vs the 86.0us kernel: out stored via __stcs (streaming, no
// L2 write-allocate pollution of the proj table / x).
// ============================================================================
#define STILE_BUF (TILE_E * ROW_PAD)          // 8704 floats
#define SMEM_FLOATS (1024 + 2 * STILE_BUF)    // 18432 floats = 73728 B

__global__ __launch_bounds__(TILE_E) void edge_kernel(const int* __restrict__ ei,
                                                      const float* __restrict__ ee,
                                                      float* __restrict__ out,
                                                      int n_edges, int n_tiles) {
    extern __shared__ float smem[];
    float* swE   = smem;                       // 512 floats
    int*   sei   = (int*)(smem + 512);         // 512 ints
    float* stile = smem + 1024;

    int t = threadIdx.x;

    // weights (512 floats = 128 float4, one per thread) + bias
    reinterpret_cast<float4*>(swE)[t] = reinterpret_cast<const float4*>(g_weffE)[t];
    float bh[8];
    #pragma unroll
    for (int h = 0; h < 8; h++) bh[h] = g_beff[h];

    const float4* ee4 = reinterpret_cast<const float4*>(ee);
    long total_f4 = (long)n_edges * 16;

    auto stage = [&](int buf, int tile) {
        if (tile < n_tiles) {
            long base = (long)tile * TILE_E * 16;
            float* dstb = stile + buf * STILE_BUF;
            #pragma unroll
            for (int i = 0; i < 16; i++) {
                int f   = i * TILE_E + t;
                int row = f >> 4;
                int col = f & 15;
                uint32_t d = smem_u32(dstb + row * ROW_PAD + col * 4);
                const float4* s = ee4 + base + f;
                int sz = (base + f < total_f4) ? 16 : 0;
                asm volatile("cp.async.cg.shared.global [%0], [%1], 16, %2;\n"
                             :: "r"(d), "l"(s), "r"(sz));
            }
            // indices: 256 ints (128 origin, 128 dest), 16B chunks by threads 0..63
            if (t < 64) {
                int half = t >> 5;           // 0 = origin, 1 = dest
                int q    = t & 31;
                int e0   = tile * TILE_E;
                const int* s = ei + (size_t)half * n_edges + e0 + q * 4;
                uint32_t d = smem_u32(sei + buf * 256 + half * 128 + q * 4);
                int rem = n_edges - (e0 + q * 4);
                int sz  = rem >= 4 ? 16 : (rem > 0 ? rem * 4 : 0);
                asm volatile("cp.async.cg.shared.global [%0], [%1], 16, %2;\n"
                             :: "r"(d), "l"(s), "r"(sz));
            }
        }
        asm volatile("cp.async.commit_group;\n");
    };

    int stride = gridDim.x;
    int tile   = blockIdx.x;
    stage(0, tile);
    stage(1, tile + stride);

    int buf = 0;
    for (; tile < n_tiles; tile += stride) {
        asm volatile("cp.async.wait_group 1;\n");
        __syncthreads();

        int e = tile * TILE_E + t;
        if (e < n_edges) {
            int o = sei[buf * 256 + t];
            int d = sei[buf * 256 + 128 + t];
            const float4* po = reinterpret_cast<const float4*>(g_proj + (size_t)o * 16);
            const float4* pd = reinterpret_cast<const float4*>(g_proj + (size_t)d * 16 + 8);
            float4 a0 = __ldg(po), a1 = __ldg(po + 1);
            float4 b0 = __ldg(pd), b1 = __ldg(pd + 1);

            float acc[8];
            acc[0] = a0.x + b0.x + bh[0];  acc[1] = a0.y + b0.y + bh[1];
            acc[2] = a0.z + b0.z + bh[2];  acc[3] = a0.w + b0.w + bh[3];
            acc[4] = a1.x + b1.x + bh[4];  acc[5] = a1.y + b1.y + bh[5];
            acc[6] = a1.z + b1.z + bh[6];  acc[7] = a1.w + b1.w + bh[7];

            const float* rowp = stile + buf * STILE_BUF + t * ROW_PAD;
            #pragma unroll
            for (int c = 0; c < 16; c++) {
                float4 v = *reinterpret_cast<const float4*>(rowp + c * 4);
                float vs[4] = {v.x, v.y, v.z, v.w};
                #pragma unroll
                for (int j = 0; j < 4; j++) {
                    int k = c * 4 + j;
                    const float4* w = reinterpret_cast<const float4*>(swE + k * 8);
                    float4 w0 = w[0], w1 = w[1];
                    acc[0] += vs[j] * w0.x;  acc[1] += vs[j] * w0.y;
                    acc[2] += vs[j] * w0.z;  acc[3] += vs[j] * w0.w;
                    acc[4] += vs[j] * w1.x;  acc[5] += vs[j] * w1.y;
                    acc[6] += vs[j] * w1.z;  acc[7] += vs[j] * w1.w;
                }
            }

            float4* op = reinterpret_cast<float4*>(out + (size_t)e * HEADS);
            __stcs(op,     make_float4(acc[0], acc[1], acc[2], acc[3]));
            __stcs(op + 1, make_float4(acc[4], acc[5], acc[6], acc[7]));
        }
        __syncthreads();                 // all reads of buf done before restaging

        stage(buf, tile + 2 * stride);   // prefetch two tiles ahead into freed buf
        buf ^= 1;
    }
}

// ============================================================================
// launcher
// ============================================================================
extern "C" void kernel_launch(void* const* d_in, const int* in_sizes, int n_in,
                              void* d_out, int out_size) {
    const float* x   = (const float*)d_in[0];
    const int*   ei  = (const int*)d_in[1];
    const float* ee  = (const float*)d_in[2];
    const float* W1  = (const float*)d_in[3];
    const float* b1  = (const float*)d_in[4];
    const float* W2  = (const float*)d_in[5];
    const float* b2  = (const float*)d_in[6];
    float*       out = (float*)d_out;

    int n_nodes = in_sizes[0] / D_IN;
    int n_edges = in_sizes[1] / 2;

    // Allow 72 KB dynamic smem for edge_kernel (idempotent; not a stream op).
    static bool attr_set = false;   // value identical every call -> deterministic
    if (!attr_set) {
        cudaFuncSetAttribute(edge_kernel, cudaFuncAttributeMaxDynamicSharedMemorySize,
                             SMEM_FLOATS * (int)sizeof(float));
        attr_set = true;
    }

    // K1: Weff/beff prep
    {
        int warps   = TOTAL * HEADS + HEADS;
        int threads = warps * 32;
        int blocks  = (threads + 255) / 256;
        prep_kernel<<<blocks, 256>>>(W1, b1, W2, b2);
    }

    // K2: node projections — one thread per node
    {
        int blocks = (n_nodes + 255) / 256;
        node_proj_kernel<<<blocks, 256>>>(x, n_nodes);
    }

    // K3: edge pass — cp.async double-buffered tiles + streaming out stores
    {
        int n_tiles = (n_edges + TILE_E - 1) / TILE_E;
        int blocks  = 444;                  // 148 SMs x 3 resident (72KB smem each)
        if (blocks > n_tiles) blocks = n_tiles;
        edge_kernel<<<blocks, TILE_E, SMEM_FLOATS * (int)sizeof(float)>>>(
            ei, ee, out, n_edges, n_tiles);
    }
}